// round 11
// baseline (speedup 1.0000x reference)
#include <cuda_runtime.h>
#include <cuda_fp16.h>
#include <cstdint>

// ============================================================
// out = diag(1/(rowsum(adj)+beta)) @ (adj + diag(beta)) @ x @ W + bias
// R10->R11: occupancy was GRID-limited (256 CTAs / 148 SMs = 1.73/SM ->
// 13.8 warps/SM, occ 21.3%). Keep the 256B/MMA 32x32 warp tile but
// split K in 2 (grid 512, 3 CTAs/SM resident => ~24 warps/SM).
// Partials (C, rowsum) -> global scratch; tiny combine kernel applies
// scale/beta/bias epilogue.
// ============================================================

#define NN 8192
#define FF 256
#define MT 32             // CTA M tile (kernel B)
#define KS 32             // K per stage (kernel B)
#define KSPLIT 4096       // K per CTA (split-K x2)
#define NITER (KSPLIT / KS)  // 128
#define KSPA 40           // A row stride in halves (80B, ldm conflict-free)
#define KSPB 264          // B row stride in halves (528B, trans-ldm conflict-free)
#define AS_STAGE (MT * KSPA)        // 1280 halves
#define AS_STAGE_B (AS_STAGE * 2)   // 2560 B
#define BS_STAGE (KS * KSPB)        // 8448 halves
#define BS_STAGE_B (BS_STAGE * 2)   // 16896 B

#define OFF_AS    0                           // 2 stages * 2560
#define OFF_BS    (2 * AS_STAGE_B)            // 5120, 3 stages * 16896
#define SMEM_TOTAL (OFF_BS + 3 * BS_STAGE_B)  // 55808 (x3 CTAs = 167424/SM)

// kernel A strides
#define KSPA_A 72
#define KSPB_A 264

__device__ __align__(256) float  g_y[NN * FF];      // y fp32
__device__ __align__(256) __half g_yh[NN * FF];     // y fp16 (row-major)
__device__ __align__(256) float  g_part[2 * NN * FF]; // split-K partial C
__device__ __align__(256) float  g_rs[2 * NN];        // split-K partial rowsum

// ---------------- helpers ----------------
__device__ __forceinline__ uint32_t smem_u32(const void* p) {
    uint32_t a;
    asm("{ .reg .u64 t; cvta.to.shared.u64 t, %1; cvt.u32.u64 %0, t; }" : "=r"(a) : "l"(p));
    return a;
}
__device__ __forceinline__ void cp16(uint32_t dst, const void* src) {
    asm volatile("cp.async.cg.shared.global [%0], [%1], 16;" :: "r"(dst), "l"(src));
}
__device__ __forceinline__ void cp_commit() {
    asm volatile("cp.async.commit_group;" ::: "memory");
}
__device__ __forceinline__ void ldm_x4(uint32_t* r, uint32_t addr) {
    asm volatile("ldmatrix.sync.aligned.m8n8.x4.shared.b16 {%0,%1,%2,%3}, [%4];"
        : "=r"(r[0]), "=r"(r[1]), "=r"(r[2]), "=r"(r[3]) : "r"(addr));
}
__device__ __forceinline__ void ldm_x4_t(uint32_t* r, uint32_t addr) {
    asm volatile("ldmatrix.sync.aligned.m8n8.x4.trans.shared.b16 {%0,%1,%2,%3}, [%4];"
        : "=r"(r[0]), "=r"(r[1]), "=r"(r[2]), "=r"(r[3]) : "r"(addr));
}
__device__ __forceinline__ void mma_f16(float* c, const uint32_t* a, uint32_t b0, uint32_t b1) {
    asm volatile(
        "mma.sync.aligned.m16n8k16.row.col.f32.f16.f16.f32 "
        "{%0,%1,%2,%3}, {%4,%5,%6,%7}, {%8,%9}, {%0,%1,%2,%3};"
        : "+f"(c[0]), "+f"(c[1]), "+f"(c[2]), "+f"(c[3])
        : "r"(a[0]), "r"(a[1]), "r"(a[2]), "r"(a[3]), "r"(b0), "r"(b1));
}

// ---------------- kernel A: y = x @ W (fp16 HMMA), writes g_y + g_yh ----------------
__global__ void __launch_bounds__(512) gemm_y_kernel(const float* __restrict__ x,
                                                     const float* __restrict__ w)
{
    __shared__ __half xs[64 * KSPA_A];
    __shared__ __half ws[64 * KSPB_A];
    const int tid = threadIdx.x;
    const int wid = tid >> 5, lane = tid & 31;
    const int g = lane >> 2, t = lane & 3;
    const int wm = wid & 1, wn = wid >> 1;
    const int m0 = blockIdx.x * 64;
    const int mt8 = lane >> 3, r8 = lane & 7;

    const uint32_t a_lm = smem_u32(xs) +
        (((wm * 32 + (mt8 & 1) * 8 + r8) * KSPA_A + (mt8 >> 1) * 8) * 2);
    const uint32_t b_lm = smem_u32(ws) +
        (((r8 + (mt8 & 1) * 8) * KSPB_A + wn * 32 + (lane >> 4) * 8) * 2);

    float acc[2][4][4];
    #pragma unroll
    for (int i = 0; i < 2; i++)
        #pragma unroll
        for (int j = 0; j < 4; j++)
            #pragma unroll
            for (int q = 0; q < 4; q++) acc[i][j][q] = 0.f;

    const int xr = tid >> 3, xq = tid & 7;
    for (int c = 0; c < 4; c++) {
        const int k0 = c * 64;
        {
            const float4 v0 = *(const float4*)&x[(size_t)(m0 + xr) * FF + k0 + xq * 8];
            const float4 v1 = *(const float4*)&x[(size_t)(m0 + xr) * FF + k0 + xq * 8 + 4];
            __half2 h[4];
            h[0] = __floats2half2_rn(v0.x, v0.y); h[1] = __floats2half2_rn(v0.z, v0.w);
            h[2] = __floats2half2_rn(v1.x, v1.y); h[3] = __floats2half2_rn(v1.z, v1.w);
            *(uint4*)&xs[xr * KSPA_A + xq * 8] = make_uint4(
                *(uint32_t*)&h[0], *(uint32_t*)&h[1], *(uint32_t*)&h[2], *(uint32_t*)&h[3]);
        }
        {
            #pragma unroll
            for (int j2 = 0; j2 < 4; j2++) {
                const float4 u0 = *(const float4*)&w[(size_t)(k0 + xr) * FF + xq * 32 + j2 * 8];
                const float4 u1 = *(const float4*)&w[(size_t)(k0 + xr) * FF + xq * 32 + j2 * 8 + 4];
                __half2 h[4];
                h[0] = __floats2half2_rn(u0.x, u0.y); h[1] = __floats2half2_rn(u0.z, u0.w);
                h[2] = __floats2half2_rn(u1.x, u1.y); h[3] = __floats2half2_rn(u1.z, u1.w);
                *(uint4*)&ws[xr * KSPB_A + xq * 32 + j2 * 8] = make_uint4(
                    *(uint32_t*)&h[0], *(uint32_t*)&h[1], *(uint32_t*)&h[2], *(uint32_t*)&h[3]);
            }
        }
        __syncthreads();
        #pragma unroll
        for (int kk = 0; kk < 4; kk++) {
            uint32_t a0[4], a1[4];
            ldm_x4(a0, a_lm + kk * 32);
            ldm_x4(a1, a_lm + kk * 32 + 16 * KSPA_A * 2);
            uint32_t bf[2][4];
            #pragma unroll
            for (int p = 0; p < 2; p++)
                ldm_x4_t(bf[p], b_lm + (uint32_t)(kk * 16 * KSPB_A + p * 16) * 2);
            #pragma unroll
            for (int p = 0; p < 2; p++) {
                mma_f16(acc[0][2 * p],     a0, bf[p][0], bf[p][1]);
                mma_f16(acc[1][2 * p],     a1, bf[p][0], bf[p][1]);
                mma_f16(acc[0][2 * p + 1], a0, bf[p][2], bf[p][3]);
                mma_f16(acc[1][2 * p + 1], a1, bf[p][2], bf[p][3]);
            }
        }
        __syncthreads();
    }

    #pragma unroll
    for (int mi = 0; mi < 2; mi++) {
        const int lm = wm * 32 + mi * 16 + g;
        #pragma unroll
        for (int nj = 0; nj < 4; nj++) {
            const int n = wn * 32 + nj * 8 + 2 * t;
            const float* cc = acc[mi][nj];
            const size_t b0 = (size_t)(m0 + lm) * FF + n;
            const size_t b1 = (size_t)(m0 + lm + 8) * FF + n;
            *(float2*)&g_y[b0] = make_float2(cc[0], cc[1]);
            *(float2*)&g_y[b1] = make_float2(cc[2], cc[3]);
            __half2 h0 = __floats2half2_rn(cc[0], cc[1]);
            __half2 h1 = __floats2half2_rn(cc[2], cc[3]);
            *(__half2*)&g_yh[b0] = h0;
            *(__half2*)&g_yh[b1] = h1;
        }
    }
}

// ---------------- kernel B: partial C = adj[:, kslice] @ y[kslice] ----------------
// 256 thr, 8 warps, warp tile 32x32, split-K x2, 3 CTAs/SM.
__global__ void __launch_bounds__(256, 3) gcn_mma_kernel(
    const float* __restrict__ adj)
{
    extern __shared__ char smem[];
    __half* As = (__half*)(smem + OFF_AS);
    const uint32_t sb = smem_u32(smem);

    const int tid = threadIdx.x;
    const int wn = tid >> 5, lane = tid & 31;
    const int g = lane >> 2, t = lane & 3;
    const int m0 = blockIdx.x * MT;
    const int ksl = blockIdx.y;             // 0 or 1
    const int k0 = ksl * KSPLIT;

    // A: 8 threads per row, one float4 each (KS=32)
    const int ar = tid >> 3, acq = tid & 7;
    const float* aptr = adj + (size_t)(m0 + ar) * NN + k0 + acq * 4;
    __half* const a_st = As + ar * KSPA + acq * 4;
    // B: 32 threads per k-row, contiguous 16B; 8 rows/pass, 4 passes/stage
    const int br = tid >> 5, bq = tid & 31;
    const __half* bptr = g_yh + (size_t)(k0 + br) * FF + bq * 8;
    const uint32_t b_dst = sb + OFF_BS + (br * KSPB) * 2 + bq * 16;

    const int mt8 = lane >> 3, r8 = lane & 7;
    const uint32_t a_lm = sb + OFF_AS +
        ((((mt8 & 1) * 8 + r8) * KSPA + (mt8 >> 1) * 8) * 2);
    const uint32_t b_lm = sb + OFF_BS +
        (((r8 + (mt8 & 1) * 8) * KSPB + wn * 32 + (mt8 >> 1) * 8) * 2);

    float rs_local = 0.f;
    float acc[2][4][4];
    #pragma unroll
    for (int i = 0; i < 2; i++)
        #pragma unroll
        for (int j = 0; j < 4; j++)
            #pragma unroll
            for (int q = 0; q < 4; q++) acc[i][j][q] = 0.f;

    float4 ra[2];

    // ---- prologue ----
    #pragma unroll
    for (int s = 0; s < 2; s++) {
        #pragma unroll
        for (int c = 0; c < 4; c++)
            cp16(b_dst + s * BS_STAGE_B + c * (8 * KSPB * 2),
                 (const void*)(bptr + ((size_t)s * KS + c * 8) * FF));
        cp_commit();
    }
    ra[0] = *(const float4*)(aptr);
    ra[1] = *(const float4*)(aptr + KS);
    {
        const float4 v = ra[0];
        rs_local += v.x + v.y + v.z + v.w;
        __half2 h0 = __floats2half2_rn(v.x, v.y), h1 = __floats2half2_rn(v.z, v.w);
        *(uint2*)a_st = make_uint2(*(uint32_t*)&h0, *(uint32_t*)&h1);
    }

    // ---- main loop (single barrier, 3-stage B ring) ----
    for (int i = 0; i < NITER; i++) {
        const int bbuf = i % 3;

        if (i + 2 < NITER)
            ra[i & 1] = *(const float4*)(aptr + (size_t)(i + 2) * KS);

        if (i < NITER - 1) { asm volatile("cp.async.wait_group 1;" ::: "memory"); }
        else               { asm volatile("cp.async.wait_group 0;" ::: "memory"); }
        __syncthreads();

        if (i + 1 < NITER) {
            const float4 v = ra[(i + 1) & 1];
            rs_local += v.x + v.y + v.z + v.w;
            __half2 h0 = __floats2half2_rn(v.x, v.y), h1 = __floats2half2_rn(v.z, v.w);
            *(uint2*)(a_st + ((i + 1) & 1) * AS_STAGE) =
                make_uint2(*(uint32_t*)&h0, *(uint32_t*)&h1);
        }
        if (i + 2 < NITER) {
            const uint32_t bd = b_dst + ((i + 2) % 3) * BS_STAGE_B;
            const __half* bp = bptr + (size_t)(i + 2) * KS * FF;
            #pragma unroll
            for (int c = 0; c < 4; c++)
                cp16(bd + c * (8 * KSPB * 2), (const void*)(bp + (size_t)c * 8 * FF));
            cp_commit();
        }

        // ---- compute stage i ----
        const uint32_t aB = a_lm + (i & 1) * AS_STAGE_B;
        const uint32_t bB = b_lm + bbuf * BS_STAGE_B;
        #pragma unroll
        for (int kk = 0; kk < 2; kk++) {
            uint32_t a0[4], a1[4], bf0[4], bf1[4];
            ldm_x4(a0, aB + kk * 32);
            ldm_x4(a1, aB + kk * 32 + 16 * KSPA * 2);
            ldm_x4_t(bf0, bB + (uint32_t)(kk * 16 * KSPB) * 2);
            ldm_x4_t(bf1, bB + (uint32_t)(kk * 16 * KSPB) * 2 + 32);
            mma_f16(acc[0][0], a0, bf0[0], bf0[1]);
            mma_f16(acc[0][1], a0, bf0[2], bf0[3]);
            mma_f16(acc[1][0], a1, bf0[0], bf0[1]);
            mma_f16(acc[1][1], a1, bf0[2], bf0[3]);
            mma_f16(acc[0][2], a0, bf1[0], bf1[1]);
            mma_f16(acc[0][3], a0, bf1[2], bf1[3]);
            mma_f16(acc[1][2], a1, bf1[0], bf1[1]);
            mma_f16(acc[1][3], a1, bf1[2], bf1[3]);
        }
    }

    // ---- partial rowsum: 8 consecutive lanes per row ----
    float rs = rs_local;
    rs += __shfl_xor_sync(0xffffffffu, rs, 1);
    rs += __shfl_xor_sync(0xffffffffu, rs, 2);
    rs += __shfl_xor_sync(0xffffffffu, rs, 4);
    if ((tid & 7) == 0) g_rs[(size_t)ksl * NN + m0 + ar] = rs;

    // ---- write partial C ----
    float* pout = g_part + (size_t)ksl * NN * FF;
    #pragma unroll
    for (int mi = 0; mi < 2; mi++) {
        const int lm = mi * 16 + g;
        #pragma unroll
        for (int nj = 0; nj < 4; nj++) {
            const int n = wn * 32 + nj * 8 + 2 * t;
            const float* cc = acc[mi][nj];
            *(float2*)&pout[(size_t)(m0 + lm) * FF + n]     = make_float2(cc[0], cc[1]);
            *(float2*)&pout[(size_t)(m0 + lm + 8) * FF + n] = make_float2(cc[2], cc[3]);
        }
    }
}

// ---------------- combine: out = scale*(P0+P1+beta*y) + bias ----------------
__global__ void __launch_bounds__(256) combine_kernel(
    const float* __restrict__ beta,
    const float* __restrict__ bias,
    float* __restrict__ out)
{
    const int idx = blockIdx.x * 256 + threadIdx.x;   // 1 thread = 4 floats
    const int m = idx >> 6;
    const int n = (idx & 63) * 4;
    const float be = beta[m];
    const float sc = 1.0f / (g_rs[m] + g_rs[NN + m] + be);
    const size_t off = (size_t)m * FF + n;
    const float4 p0 = *(const float4*)&g_part[off];
    const float4 p1 = *(const float4*)&g_part[(size_t)NN * FF + off];
    const float4 yv = *(const float4*)&g_y[off];
    const float4 bv = *(const float4*)&bias[n];
    float4 o;
    o.x = sc * (p0.x + p1.x + be * yv.x) + bv.x;
    o.y = sc * (p0.y + p1.y + be * yv.y) + bv.y;
    o.z = sc * (p0.z + p1.z + be * yv.z) + bv.z;
    o.w = sc * (p0.w + p1.w + be * yv.w) + bv.w;
    *(float4*)&out[off] = o;
}

// ---------------- launch ----------------
extern "C" void kernel_launch(void* const* d_in, const int* in_sizes, int n_in,
                              void* d_out, int out_size)
{
    const float *x = nullptr, *adj = nullptr, *w = nullptr, *bias = nullptr, *beta = nullptr;
    for (int i = 0; i < n_in; i++) {
        switch (in_sizes[i]) {
            case NN * FF:   x    = (const float*)d_in[i]; break;
            case 67108864:  adj  = (const float*)d_in[i]; break;
            case FF * FF:   w    = (const float*)d_in[i]; break;
            case FF:        bias = (const float*)d_in[i]; break;
            case NN:        beta = (const float*)d_in[i]; break;
            default: break;
        }
    }
    float* out = (float*)d_out;

    cudaFuncSetAttribute(gcn_mma_kernel, cudaFuncAttributeMaxDynamicSharedMemorySize, SMEM_TOTAL);

    gemm_y_kernel<<<NN / 64, 512>>>(x, w);
    gcn_mma_kernel<<<dim3(NN / MT, 2), 256, SMEM_TOTAL>>>(adj);
    combine_kernel<<<(NN * FF) / (256 * 4), 256>>>(beta, bias, out);
}

// round 12
// speedup vs baseline: 1.3585x; 1.3585x over previous
#include <cuda_runtime.h>
#include <cuda_fp16.h>
#include <cstdint>

// ============================================================
// out = diag(1/(rowsum(adj)+beta)) @ (adj + diag(beta)) @ x @ W + bias
// R11->R12: warp tile 32x64 (192B LDSM per MMA, was 384 in best-so-far R9)
// at R9's proven residency (grid 256, 2 CTAs/SM, ~28 warps/SM):
// 256 thr, 8 warps (2m x 4n), CTA 64x256, MT=64 + split-K x2.
// MT=64 also halves y L2 re-reads. Single-barrier 3-stage B ring.
// ============================================================

#define NN 8192
#define FF 256
#define MT 64             // CTA M tile (kernel B)
#define KS 32             // K per stage (kernel B)
#define KSPLIT 4096       // K per CTA (split-K x2)
#define NITER (KSPLIT / KS)  // 128
#define KSPA 40           // A row stride in halves (80B)
#define KSPB 264          // B row stride in halves (528B, trans-ldm conflict-free)
#define AS_STAGE (MT * KSPA)        // 2560 halves
#define AS_STAGE_B (AS_STAGE * 2)   // 5120 B
#define BS_STAGE (KS * KSPB)        // 8448 halves
#define BS_STAGE_B (BS_STAGE * 2)   // 16896 B

#define OFF_AS    0                           // 2 stages * 5120
#define OFF_BS    (2 * AS_STAGE_B)            // 10240, 3 stages * 16896
#define SMEM_TOTAL (OFF_BS + 3 * BS_STAGE_B)  // 60928 (x2 CTAs = 121856/SM)

// kernel A strides
#define KSPA_A 72
#define KSPB_A 264

__device__ __align__(256) float  g_y[NN * FF];        // y fp32
__device__ __align__(256) __half g_yh[NN * FF];       // y fp16 (row-major)
__device__ __align__(256) float  g_part[2 * NN * FF]; // split-K partial C
__device__ __align__(256) float  g_rs[2 * NN];        // split-K partial rowsum

// ---------------- helpers ----------------
__device__ __forceinline__ uint32_t smem_u32(const void* p) {
    uint32_t a;
    asm("{ .reg .u64 t; cvta.to.shared.u64 t, %1; cvt.u32.u64 %0, t; }" : "=r"(a) : "l"(p));
    return a;
}
__device__ __forceinline__ void cp16(uint32_t dst, const void* src) {
    asm volatile("cp.async.cg.shared.global [%0], [%1], 16;" :: "r"(dst), "l"(src));
}
__device__ __forceinline__ void cp_commit() {
    asm volatile("cp.async.commit_group;" ::: "memory");
}
__device__ __forceinline__ void ldm_x4(uint32_t* r, uint32_t addr) {
    asm volatile("ldmatrix.sync.aligned.m8n8.x4.shared.b16 {%0,%1,%2,%3}, [%4];"
        : "=r"(r[0]), "=r"(r[1]), "=r"(r[2]), "=r"(r[3]) : "r"(addr));
}
__device__ __forceinline__ void ldm_x4_t(uint32_t* r, uint32_t addr) {
    asm volatile("ldmatrix.sync.aligned.m8n8.x4.trans.shared.b16 {%0,%1,%2,%3}, [%4];"
        : "=r"(r[0]), "=r"(r[1]), "=r"(r[2]), "=r"(r[3]) : "r"(addr));
}
__device__ __forceinline__ void mma_f16(float* c, const uint32_t* a, uint32_t b0, uint32_t b1) {
    asm volatile(
        "mma.sync.aligned.m16n8k16.row.col.f32.f16.f16.f32 "
        "{%0,%1,%2,%3}, {%4,%5,%6,%7}, {%8,%9}, {%0,%1,%2,%3};"
        : "+f"(c[0]), "+f"(c[1]), "+f"(c[2]), "+f"(c[3])
        : "r"(a[0]), "r"(a[1]), "r"(a[2]), "r"(a[3]), "r"(b0), "r"(b1));
}

// ---------------- kernel A: y = x @ W (fp16 HMMA), writes g_y + g_yh ----------------
__global__ void __launch_bounds__(512) gemm_y_kernel(const float* __restrict__ x,
                                                     const float* __restrict__ w)
{
    __shared__ __half xs[64 * KSPA_A];
    __shared__ __half ws[64 * KSPB_A];
    const int tid = threadIdx.x;
    const int wid = tid >> 5, lane = tid & 31;
    const int g = lane >> 2, t = lane & 3;
    const int wm = wid & 1, wn = wid >> 1;
    const int m0 = blockIdx.x * 64;
    const int mt8 = lane >> 3, r8 = lane & 7;

    const uint32_t a_lm = smem_u32(xs) +
        (((wm * 32 + (mt8 & 1) * 8 + r8) * KSPA_A + (mt8 >> 1) * 8) * 2);
    const uint32_t b_lm = smem_u32(ws) +
        (((r8 + (mt8 & 1) * 8) * KSPB_A + wn * 32 + (lane >> 4) * 8) * 2);

    float acc[2][4][4];
    #pragma unroll
    for (int i = 0; i < 2; i++)
        #pragma unroll
        for (int j = 0; j < 4; j++)
            #pragma unroll
            for (int q = 0; q < 4; q++) acc[i][j][q] = 0.f;

    const int xr = tid >> 3, xq = tid & 7;
    for (int c = 0; c < 4; c++) {
        const int k0 = c * 64;
        {
            const float4 v0 = *(const float4*)&x[(size_t)(m0 + xr) * FF + k0 + xq * 8];
            const float4 v1 = *(const float4*)&x[(size_t)(m0 + xr) * FF + k0 + xq * 8 + 4];
            __half2 h[4];
            h[0] = __floats2half2_rn(v0.x, v0.y); h[1] = __floats2half2_rn(v0.z, v0.w);
            h[2] = __floats2half2_rn(v1.x, v1.y); h[3] = __floats2half2_rn(v1.z, v1.w);
            *(uint4*)&xs[xr * KSPA_A + xq * 8] = make_uint4(
                *(uint32_t*)&h[0], *(uint32_t*)&h[1], *(uint32_t*)&h[2], *(uint32_t*)&h[3]);
        }
        {
            #pragma unroll
            for (int j2 = 0; j2 < 4; j2++) {
                const float4 u0 = *(const float4*)&w[(size_t)(k0 + xr) * FF + xq * 32 + j2 * 8];
                const float4 u1 = *(const float4*)&w[(size_t)(k0 + xr) * FF + xq * 32 + j2 * 8 + 4];
                __half2 h[4];
                h[0] = __floats2half2_rn(u0.x, u0.y); h[1] = __floats2half2_rn(u0.z, u0.w);
                h[2] = __floats2half2_rn(u1.x, u1.y); h[3] = __floats2half2_rn(u1.z, u1.w);
                *(uint4*)&ws[xr * KSPB_A + xq * 32 + j2 * 8] = make_uint4(
                    *(uint32_t*)&h[0], *(uint32_t*)&h[1], *(uint32_t*)&h[2], *(uint32_t*)&h[3]);
            }
        }
        __syncthreads();
        #pragma unroll
        for (int kk = 0; kk < 4; kk++) {
            uint32_t a0[4], a1[4];
            ldm_x4(a0, a_lm + kk * 32);
            ldm_x4(a1, a_lm + kk * 32 + 16 * KSPA_A * 2);
            uint32_t bf[2][4];
            #pragma unroll
            for (int p = 0; p < 2; p++)
                ldm_x4_t(bf[p], b_lm + (uint32_t)(kk * 16 * KSPB_A + p * 16) * 2);
            #pragma unroll
            for (int p = 0; p < 2; p++) {
                mma_f16(acc[0][2 * p],     a0, bf[p][0], bf[p][1]);
                mma_f16(acc[1][2 * p],     a1, bf[p][0], bf[p][1]);
                mma_f16(acc[0][2 * p + 1], a0, bf[p][2], bf[p][3]);
                mma_f16(acc[1][2 * p + 1], a1, bf[p][2], bf[p][3]);
            }
        }
        __syncthreads();
    }

    #pragma unroll
    for (int mi = 0; mi < 2; mi++) {
        const int lm = wm * 32 + mi * 16 + g;
        #pragma unroll
        for (int nj = 0; nj < 4; nj++) {
            const int n = wn * 32 + nj * 8 + 2 * t;
            const float* cc = acc[mi][nj];
            const size_t b0 = (size_t)(m0 + lm) * FF + n;
            const size_t b1 = (size_t)(m0 + lm + 8) * FF + n;
            *(float2*)&g_y[b0] = make_float2(cc[0], cc[1]);
            *(float2*)&g_y[b1] = make_float2(cc[2], cc[3]);
            __half2 h0 = __floats2half2_rn(cc[0], cc[1]);
            __half2 h1 = __floats2half2_rn(cc[2], cc[3]);
            *(__half2*)&g_yh[b0] = h0;
            *(__half2*)&g_yh[b1] = h1;
        }
    }
}

// ---------------- kernel B: partial C = adj[:, kslice] @ y[kslice] ----------------
// 256 thr, 8 warps (2m x 4n), warp tile 32x64, CTA 64x256, split-K x2.
__global__ void __launch_bounds__(256, 2) gcn_mma_kernel(
    const float* __restrict__ adj)
{
    extern __shared__ char smem[];
    __half* As = (__half*)(smem + OFF_AS);
    const uint32_t sb = smem_u32(smem);

    const int tid = threadIdx.x;
    const int wid = tid >> 5, lane = tid & 31;
    const int g = lane >> 2, t = lane & 3;
    const int wm = wid & 1, wn = wid >> 1;      // 2 m-warps x 4 n-warps
    const int m0 = blockIdx.x * MT;
    const int ksl = blockIdx.y;                 // 0 or 1
    const int k0 = ksl * KSPLIT;

    // A: 4 threads per row, 8 floats each (KS=32)
    const int ar = tid >> 2, acq = tid & 3;
    const float* aptr = adj + (size_t)(m0 + ar) * NN + k0 + acq * 8;
    __half* const a_st = As + ar * KSPA + acq * 8;
    // B: 32 threads per k-row, contiguous 16B; 8 rows/pass, 4 passes/stage
    const int br = tid >> 5, bq = tid & 31;
    const __half* bptr = g_yh + (size_t)(k0 + br) * FF + bq * 8;
    const uint32_t b_dst = sb + OFF_BS + (br * KSPB) * 2 + bq * 16;

    const int mt8 = lane >> 3, r8 = lane & 7;
    const uint32_t a_lm = sb + OFF_AS +
        (((wm * 32 + (mt8 & 1) * 8 + r8) * KSPA + (mt8 >> 1) * 8) * 2);
    const uint32_t b_lm = sb + OFF_BS +
        (((r8 + (mt8 & 1) * 8) * KSPB + wn * 64 + (mt8 >> 1) * 8) * 2);

    float rs_local = 0.f;
    float acc[2][8][4];
    #pragma unroll
    for (int i = 0; i < 2; i++)
        #pragma unroll
        for (int j = 0; j < 8; j++)
            #pragma unroll
            for (int q = 0; q < 4; q++) acc[i][j][q] = 0.f;

    float4 ra[2][2];

    // ---- prologue: B stages 0,1 via cp.async; A stages 0,1 via LDG ----
    #pragma unroll
    for (int s = 0; s < 2; s++) {
        #pragma unroll
        for (int c = 0; c < 4; c++)
            cp16(b_dst + s * BS_STAGE_B + c * (8 * KSPB * 2),
                 (const void*)(bptr + ((size_t)s * KS + c * 8) * FF));
        cp_commit();
    }
    #pragma unroll
    for (int s = 0; s < 2; s++) {
        ra[s][0] = *(const float4*)(aptr + (size_t)s * KS);
        ra[s][1] = *(const float4*)(aptr + (size_t)s * KS + 4);
    }
    {   // STS A stage 0 + rowsum
        const float4 v0 = ra[0][0], v1 = ra[0][1];
        rs_local += v0.x + v0.y + v0.z + v0.w + v1.x + v1.y + v1.z + v1.w;
        __half2 h[4];
        h[0] = __floats2half2_rn(v0.x, v0.y); h[1] = __floats2half2_rn(v0.z, v0.w);
        h[2] = __floats2half2_rn(v1.x, v1.y); h[3] = __floats2half2_rn(v1.z, v1.w);
        *(uint4*)a_st = make_uint4(*(uint32_t*)&h[0], *(uint32_t*)&h[1],
                                   *(uint32_t*)&h[2], *(uint32_t*)&h[3]);
    }

    // ---- main loop (single barrier, 3-stage B ring) ----
    for (int i = 0; i < NITER; i++) {
        const int bbuf = i % 3;

        if (i + 2 < NITER) {
            const float* ap = aptr + (size_t)(i + 2) * KS;
            ra[i & 1][0] = *(const float4*)(ap);
            ra[i & 1][1] = *(const float4*)(ap + 4);
        }

        if (i < NITER - 1) { asm volatile("cp.async.wait_group 1;" ::: "memory"); }
        else               { asm volatile("cp.async.wait_group 0;" ::: "memory"); }
        __syncthreads();

        if (i + 1 < NITER) {   // STS A stage i+1 + rowsum
            const float4 v0 = ra[(i + 1) & 1][0], v1 = ra[(i + 1) & 1][1];
            rs_local += v0.x + v0.y + v0.z + v0.w + v1.x + v1.y + v1.z + v1.w;
            __half2 h[4];
            h[0] = __floats2half2_rn(v0.x, v0.y); h[1] = __floats2half2_rn(v0.z, v0.w);
            h[2] = __floats2half2_rn(v1.x, v1.y); h[3] = __floats2half2_rn(v1.z, v1.w);
            *(uint4*)(a_st + ((i + 1) & 1) * AS_STAGE) = make_uint4(
                *(uint32_t*)&h[0], *(uint32_t*)&h[1], *(uint32_t*)&h[2], *(uint32_t*)&h[3]);
        }
        if (i + 2 < NITER) {   // cp.async B stage i+2 into buf (i+2)%3
            const uint32_t bd = b_dst + ((i + 2) % 3) * BS_STAGE_B;
            const __half* bp = bptr + (size_t)(i + 2) * KS * FF;
            #pragma unroll
            for (int c = 0; c < 4; c++)
                cp16(bd + c * (8 * KSPB * 2), (const void*)(bp + (size_t)c * 8 * FF));
            cp_commit();
        }

        // ---- compute stage i (warp tile 32x64, 2 kk chunks) ----
        const uint32_t aB = a_lm + (i & 1) * AS_STAGE_B;
        const uint32_t bB = b_lm + bbuf * BS_STAGE_B;
        #pragma unroll
        for (int kk = 0; kk < 2; kk++) {
            uint32_t a0[4], a1[4];
            ldm_x4(a0, aB + kk * 32);
            ldm_x4(a1, aB + kk * 32 + 16 * KSPA * 2);
            uint32_t bf[4][4];
            #pragma unroll
            for (int j = 0; j < 4; j++)
                ldm_x4_t(bf[j], bB + (uint32_t)(kk * 16 * KSPB) * 2 + j * 32);
            #pragma unroll
            for (int j = 0; j < 4; j++) {
                mma_f16(acc[0][2 * j],     a0, bf[j][0], bf[j][1]);
                mma_f16(acc[0][2 * j + 1], a0, bf[j][2], bf[j][3]);
                mma_f16(acc[1][2 * j],     a1, bf[j][0], bf[j][1]);
                mma_f16(acc[1][2 * j + 1], a1, bf[j][2], bf[j][3]);
            }
        }
    }

    // ---- partial rowsum: 4 consecutive lanes per row ----
    float rs = rs_local;
    rs += __shfl_xor_sync(0xffffffffu, rs, 1);
    rs += __shfl_xor_sync(0xffffffffu, rs, 2);
    if ((tid & 3) == 0) g_rs[(size_t)ksl * NN + m0 + ar] = rs;

    // ---- write partial C ----
    float* pout = g_part + (size_t)ksl * NN * FF;
    #pragma unroll
    for (int mi = 0; mi < 2; mi++) {
        const int lm = wm * 32 + mi * 16 + g;
        #pragma unroll
        for (int nj = 0; nj < 8; nj++) {
            const int n = wn * 64 + nj * 8 + 2 * t;
            const float* cc = acc[mi][nj];
            *(float2*)&pout[(size_t)(m0 + lm) * FF + n]     = make_float2(cc[0], cc[1]);
            *(float2*)&pout[(size_t)(m0 + lm + 8) * FF + n] = make_float2(cc[2], cc[3]);
        }
    }
}

// ---------------- combine: out = scale*(P0+P1+beta*y) + bias ----------------
__global__ void __launch_bounds__(256) combine_kernel(
    const float* __restrict__ beta,
    const float* __restrict__ bias,
    float* __restrict__ out)
{
    const int idx = blockIdx.x * 256 + threadIdx.x;   // 1 thread = 4 floats
    const int m = idx >> 6;
    const int n = (idx & 63) * 4;
    const float be = beta[m];
    const float sc = 1.0f / (g_rs[m] + g_rs[NN + m] + be);
    const size_t off = (size_t)m * FF + n;
    const float4 p0 = *(const float4*)&g_part[off];
    const float4 p1 = *(const float4*)&g_part[(size_t)NN * FF + off];
    const float4 yv = *(const float4*)&g_y[off];
    const float4 bv = *(const float4*)&bias[n];
    float4 o;
    o.x = sc * (p0.x + p1.x + be * yv.x) + bv.x;
    o.y = sc * (p0.y + p1.y + be * yv.y) + bv.y;
    o.z = sc * (p0.z + p1.z + be * yv.z) + bv.z;
    o.w = sc * (p0.w + p1.w + be * yv.w) + bv.w;
    *(float4*)&out[off] = o;
}

// ---------------- launch ----------------
extern "C" void kernel_launch(void* const* d_in, const int* in_sizes, int n_in,
                              void* d_out, int out_size)
{
    const float *x = nullptr, *adj = nullptr, *w = nullptr, *bias = nullptr, *beta = nullptr;
    for (int i = 0; i < n_in; i++) {
        switch (in_sizes[i]) {
            case NN * FF:   x    = (const float*)d_in[i]; break;
            case 67108864:  adj  = (const float*)d_in[i]; break;
            case FF * FF:   w    = (const float*)d_in[i]; break;
            case FF:        bias = (const float*)d_in[i]; break;
            case NN:        beta = (const float*)d_in[i]; break;
            default: break;
        }
    }
    float* out = (float*)d_out;

    cudaFuncSetAttribute(gcn_mma_kernel, cudaFuncAttributeMaxDynamicSharedMemorySize, SMEM_TOTAL);

    gemm_y_kernel<<<NN / 64, 512>>>(x, w);
    gcn_mma_kernel<<<dim3(NN / MT, 2), 256, SMEM_TOTAL>>>(adj);
    combine_kernel<<<(NN * FF) / (256 * 4), 256>>>(beta, bias, out);
}